// round 8
// baseline (speedup 1.0000x reference)
#include <cuda_runtime.h>
#include <cuda_bf16.h>

// B=8192, L=1, K=32, H=1024.
// k1: barrier-free cdist stream (1 GiB), ~86% HBM. FROZEN.
// k2: MLP tail — smem W1 (stride-100), 8 batches/CTA. R7 fix: slot loop kept
//     rolled (#pragma unroll 1) + launch_bounds(256,4) so regs<=64 and
//     occ rises from 1 to 4 CTAs/SM (R6 had regs=132 -> 7 serial waves).

#define KK 32
#define HH 1024
#define BB 8192

__device__ float g_cd[BB * KK];   // scratch: sqrt'd context distances (1 MB)

// ---------------- Kernel 1: streaming cdist, one CTA per batch ----------------
__global__ __launch_bounds__(256, 8) void cdist_kernel(
    const float* __restrict__ cache_hidden,
    const float* __restrict__ hiddens)
{
    const int b    = blockIdx.x;
    const int warp = threadIdx.x >> 5;
    const int lane = threadIdx.x & 31;

    const float4* C4    = (const float4*)(cache_hidden + (size_t)b * HH);
    const float4* Hbase = (const float4*)(hiddens + (size_t)b * KK * HH)
                        + (size_t)warp * 4 * 256;

    float a0 = 0.f, a1 = 0.f, a2 = 0.f, a3 = 0.f;
    #pragma unroll
    for (int it = 0; it < 8; it++) {
        int idx = it * 32 + lane;                  // coalesced 512B per LDG
        float4 c  = __ldg(&C4[idx]);               // L1-hit after first warp
        float4 x0 = __ldcs(Hbase + idx);
        float4 x1 = __ldcs(Hbase + 256 + idx);
        float4 x2 = __ldcs(Hbase + 512 + idx);
        float4 x3 = __ldcs(Hbase + 768 + idx);
        float d;
        d = c.x - x0.x; a0 += d * d;  d = c.y - x0.y; a0 += d * d;
        d = c.z - x0.z; a0 += d * d;  d = c.w - x0.w; a0 += d * d;
        d = c.x - x1.x; a1 += d * d;  d = c.y - x1.y; a1 += d * d;
        d = c.z - x1.z; a1 += d * d;  d = c.w - x1.w; a1 += d * d;
        d = c.x - x2.x; a2 += d * d;  d = c.y - x2.y; a2 += d * d;
        d = c.z - x2.z; a2 += d * d;  d = c.w - x2.w; a2 += d * d;
        d = c.x - x3.x; a3 += d * d;  d = c.y - x3.y; a3 += d * d;
        d = c.z - x3.z; a3 += d * d;  d = c.w - x3.w; a3 += d * d;
    }
    #pragma unroll
    for (int o = 16; o; o >>= 1) {
        a0 += __shfl_xor_sync(0xffffffffu, a0, o);
        a1 += __shfl_xor_sync(0xffffffffu, a1, o);
        a2 += __shfl_xor_sync(0xffffffffu, a2, o);
        a3 += __shfl_xor_sync(0xffffffffu, a3, o);
    }
    if (lane < 4) {
        float a = (lane == 0) ? a0 : (lane == 1) ? a1 : (lane == 2) ? a2 : a3;
        g_cd[b * KK + warp * 4 + lane] = sqrtf(a);
    }
}

// ---------------- Kernel 2: MLP tail, 8 batches per CTA, smem W1 ----------------
#define W1S 100   // padded row stride (floats); 25 float4 -> conflict-free LDS.128

__global__ __launch_bounds__(256, 4) void mlp_kernel(
    const int*   __restrict__ vals,
    const float* __restrict__ distances,
    const float* __restrict__ W1,
    const float* __restrict__ b1,
    const float* __restrict__ W2,
    const float* __restrict__ b2,
    float* __restrict__ out, int N)
{
    __shared__ __align__(16) float sW1[64 * W1S];   // 25.6 KB
    __shared__ __align__(16) float sx[8][96];
    __shared__ float shid[8][64];

    const int b0   = blockIdx.x * 8;
    const int tid  = threadIdx.x;
    const int warp = tid >> 5;
    const int lane = tid & 31;

    // stage W1: 1536 float4, coalesced, rows repadded to stride 100
    {
        const float4* g = (const float4*)W1;
        #pragma unroll
        for (int i = 0; i < 6; i++) {
            int m4 = tid + i * 256;
            float4 v = g[m4];
            int m = m4 * 4;
            int r = m / 96, c = m - r * 96;          // float4 never crosses a row
            *(float4*)&sW1[r * W1S + c] = v;
        }
    }

    // warps 0-7: assemble inputs for batch j = warp
    {
        const int bb = b0 + warp;
        sx[warp][lane]      = g_cd[bb * KK + lane];
        sx[warp][32 + lane] = distances[bb * KK + lane];
        int v = vals[bb * KK + lane];
        unsigned m = __match_any_sync(0xffffffffu, v);
        int isnew = (v != 0) && ((m & ((1u << lane) - 1u)) == 0);
        int cnt = isnew;
        #pragma unroll
        for (int o = 1; o < 32; o <<= 1) {
            int t = __shfl_up_sync(0xffffffffu, cnt, o);
            if (lane >= o) cnt += t;
        }
        sx[warp][64 + lane] = (float)cnt;
    }
    __syncthreads();

    // layer 1: 256 threads x 2 sequential tasks = 8 batches x 64 neurons
    {
        const int n = tid & 63;
        const float4* w4 = (const float4*)&sW1[n * W1S];
        const float bias = __ldg(&b1[n]);
        #pragma unroll 1
        for (int slot = 0; slot < 2; slot++) {
            const int j = (tid >> 6) + slot * 4;
            const float4* x4 = (const float4*)sx[j];
            float acc = bias;
            #pragma unroll
            for (int i = 0; i < 24; i++) {
                float4 w = w4[i];
                float4 x = x4[i];
                acc += w.x * x.x + w.y * x.y + w.z * x.z + w.w * x.w;
            }
            shid[j][n] = tanhf(acc);
        }
    }
    __syncthreads();

    // layer 2 + sigmoid + scale + write: warp j handles batch j
    {
        const int j = warp;
        float s = shid[j][lane] * __ldg(&W2[lane])
                + shid[j][lane + 32] * __ldg(&W2[lane + 32]);
        #pragma unroll
        for (int o = 16; o; o >>= 1) s += __shfl_xor_sync(0xffffffffu, s, o);
        s += __ldg(&b2[0]);
        float mu = 1.f / (1.f + expf(-s));
        float scale = __shfl_sync(0xffffffffu, 5.f * mu, 0);
        float cd = sx[j][lane] * scale;
        int o0 = (b0 + j) * KK + lane;
        out[o0]     = cd;
        out[N + o0] = sx[j][32 + lane] + cd;
    }
}

extern "C" void kernel_launch(void* const* d_in, const int* in_sizes, int n_in,
                              void* d_out, int out_size)
{
    const int*   vals         = (const int*)  d_in[0];
    const float* distances    = (const float*)d_in[1];
    const float* cache_hidden = (const float*)d_in[2];
    const float* hiddens      = (const float*)d_in[3];
    const float* W1           = (const float*)d_in[4];
    const float* b1           = (const float*)d_in[5];
    const float* W2           = (const float*)d_in[6];
    const float* b2           = (const float*)d_in[7];
    float* out = (float*)d_out;

    int N = in_sizes[1];              // B*L*K = 262144
    int B = N / KK;                   // 8192

    cdist_kernel<<<B, 256>>>(cache_hidden, hiddens);
    mlp_kernel<<<B / 8, 256>>>(vals, distances, W1, b1, W2, b2, out, N);
}

// round 9
// speedup vs baseline: 1.1445x; 1.1445x over previous
#include <cuda_runtime.h>
#include <cuda_bf16.h>

// B=8192, L=1, K=32, H=1024.
// k1: barrier-free cdist stream (1 GiB), ~87% HBM. FROZEN.
// k2: = R6 (fully unrolled, fast per-CTA) + launch_bounds(256,2):
//     regs 132->128 => 2 CTAs/SM instead of 1 => waves 7 -> 3.5.

#define KK 32
#define HH 1024
#define BB 8192

__device__ float g_cd[BB * KK];   // scratch: sqrt'd context distances (1 MB)

// ---------------- Kernel 1: streaming cdist, one CTA per batch ----------------
__global__ __launch_bounds__(256, 8) void cdist_kernel(
    const float* __restrict__ cache_hidden,
    const float* __restrict__ hiddens)
{
    const int b    = blockIdx.x;
    const int warp = threadIdx.x >> 5;
    const int lane = threadIdx.x & 31;

    const float4* C4    = (const float4*)(cache_hidden + (size_t)b * HH);
    const float4* Hbase = (const float4*)(hiddens + (size_t)b * KK * HH)
                        + (size_t)warp * 4 * 256;

    float a0 = 0.f, a1 = 0.f, a2 = 0.f, a3 = 0.f;
    #pragma unroll
    for (int it = 0; it < 8; it++) {
        int idx = it * 32 + lane;                  // coalesced 512B per LDG
        float4 c  = __ldg(&C4[idx]);               // L1-hit after first warp
        float4 x0 = __ldcs(Hbase + idx);
        float4 x1 = __ldcs(Hbase + 256 + idx);
        float4 x2 = __ldcs(Hbase + 512 + idx);
        float4 x3 = __ldcs(Hbase + 768 + idx);
        float d;
        d = c.x - x0.x; a0 += d * d;  d = c.y - x0.y; a0 += d * d;
        d = c.z - x0.z; a0 += d * d;  d = c.w - x0.w; a0 += d * d;
        d = c.x - x1.x; a1 += d * d;  d = c.y - x1.y; a1 += d * d;
        d = c.z - x1.z; a1 += d * d;  d = c.w - x1.w; a1 += d * d;
        d = c.x - x2.x; a2 += d * d;  d = c.y - x2.y; a2 += d * d;
        d = c.z - x2.z; a2 += d * d;  d = c.w - x2.w; a2 += d * d;
        d = c.x - x3.x; a3 += d * d;  d = c.y - x3.y; a3 += d * d;
        d = c.z - x3.z; a3 += d * d;  d = c.w - x3.w; a3 += d * d;
    }
    #pragma unroll
    for (int o = 16; o; o >>= 1) {
        a0 += __shfl_xor_sync(0xffffffffu, a0, o);
        a1 += __shfl_xor_sync(0xffffffffu, a1, o);
        a2 += __shfl_xor_sync(0xffffffffu, a2, o);
        a3 += __shfl_xor_sync(0xffffffffu, a3, o);
    }
    if (lane < 4) {
        float a = (lane == 0) ? a0 : (lane == 1) ? a1 : (lane == 2) ? a2 : a3;
        g_cd[b * KK + warp * 4 + lane] = sqrtf(a);
    }
}

// ---------------- Kernel 2: MLP tail, 8 batches per CTA, smem W1 ----------------
#define W1S 100   // padded row stride (floats); 25 float4 -> conflict-free LDS.128

__global__ __launch_bounds__(256, 2) void mlp_kernel(
    const int*   __restrict__ vals,
    const float* __restrict__ distances,
    const float* __restrict__ W1,
    const float* __restrict__ b1,
    const float* __restrict__ W2,
    const float* __restrict__ b2,
    float* __restrict__ out, int N)
{
    __shared__ __align__(16) float sW1[64 * W1S];   // 25.6 KB
    __shared__ __align__(16) float sx[8][96];
    __shared__ float shid[8][64];

    const int b0   = blockIdx.x * 8;
    const int tid  = threadIdx.x;
    const int warp = tid >> 5;
    const int lane = tid & 31;

    // stage W1: 1536 float4, coalesced, rows repadded to stride 100
    {
        const float4* g = (const float4*)W1;
        #pragma unroll
        for (int i = 0; i < 6; i++) {
            int m4 = tid + i * 256;
            float4 v = g[m4];
            int m = m4 * 4;
            int r = m / 96, c = m - r * 96;          // float4 never crosses a row
            *(float4*)&sW1[r * W1S + c] = v;
        }
    }

    // warps 0-7: assemble inputs for batch j = warp
    {
        const int bb = b0 + warp;
        sx[warp][lane]      = g_cd[bb * KK + lane];
        sx[warp][32 + lane] = distances[bb * KK + lane];
        int v = vals[bb * KK + lane];
        unsigned m = __match_any_sync(0xffffffffu, v);
        int isnew = (v != 0) && ((m & ((1u << lane) - 1u)) == 0);
        int cnt = isnew;
        #pragma unroll
        for (int o = 1; o < 32; o <<= 1) {
            int t = __shfl_up_sync(0xffffffffu, cnt, o);
            if (lane >= o) cnt += t;
        }
        sx[warp][64 + lane] = (float)cnt;
    }
    __syncthreads();

    // layer 1: 256 threads x 2 tasks = 8 batches x 64 neurons (fully unrolled)
    {
        const int n = tid & 63;
        const float4* w4 = (const float4*)&sW1[n * W1S];
        const float bias = __ldg(&b1[n]);
        #pragma unroll
        for (int slot = 0; slot < 2; slot++) {
            const int j = (tid >> 6) + slot * 4;
            const float4* x4 = (const float4*)sx[j];
            float acc = bias;
            #pragma unroll
            for (int i = 0; i < 24; i++) {
                float4 w = w4[i];
                float4 x = x4[i];
                acc += w.x * x.x + w.y * x.y + w.z * x.z + w.w * x.w;
            }
            shid[j][n] = tanhf(acc);
        }
    }
    __syncthreads();

    // layer 2 + sigmoid + scale + write: warp j handles batch j
    {
        const int j = warp;
        float s = shid[j][lane] * __ldg(&W2[lane])
                + shid[j][lane + 32] * __ldg(&W2[lane + 32]);
        #pragma unroll
        for (int o = 16; o; o >>= 1) s += __shfl_xor_sync(0xffffffffu, s, o);
        s += __ldg(&b2[0]);
        float mu = 1.f / (1.f + expf(-s));
        float scale = __shfl_sync(0xffffffffu, 5.f * mu, 0);
        float cd = sx[j][lane] * scale;
        int o0 = (b0 + j) * KK + lane;
        out[o0]     = cd;
        out[N + o0] = sx[j][32 + lane] + cd;
    }
}

extern "C" void kernel_launch(void* const* d_in, const int* in_sizes, int n_in,
                              void* d_out, int out_size)
{
    const int*   vals         = (const int*)  d_in[0];
    const float* distances    = (const float*)d_in[1];
    const float* cache_hidden = (const float*)d_in[2];
    const float* hiddens      = (const float*)d_in[3];
    const float* W1           = (const float*)d_in[4];
    const float* b1           = (const float*)d_in[5];
    const float* W2           = (const float*)d_in[6];
    const float* b2           = (const float*)d_in[7];
    float* out = (float*)d_out;

    int N = in_sizes[1];              // B*L*K = 262144
    int B = N / KK;                   // 8192

    cdist_kernel<<<B, 256>>>(cache_hidden, hiddens);
    mlp_kernel<<<B / 8, 256>>>(vals, distances, W1, b1, W2, b2, out, N);
}

// round 10
// speedup vs baseline: 1.1561x; 1.0102x over previous
#include <cuda_runtime.h>
#include <cuda_bf16.h>

// B=8192, L=1, K=32, H=1024.
// k1: barrier-free cdist stream (1 GiB), ~87% HBM. FROZEN.
// k2 R9: 16 batches/CTA (grid 512). Layer-1 interleaves 4 batches per i-step:
//   one w LDS.128 feeds 4 dot-products (x reads are broadcasts). W1 smem
//   bytes per batch drop 4x vs R8 -> crossbar-bound time ~3us chip-wide.

#define KK 32
#define HH 1024
#define BB 8192

__device__ float g_cd[BB * KK];   // scratch: sqrt'd context distances (1 MB)

// ---------------- Kernel 1: streaming cdist, one CTA per batch ----------------
__global__ __launch_bounds__(256, 8) void cdist_kernel(
    const float* __restrict__ cache_hidden,
    const float* __restrict__ hiddens)
{
    const int b    = blockIdx.x;
    const int warp = threadIdx.x >> 5;
    const int lane = threadIdx.x & 31;

    const float4* C4    = (const float4*)(cache_hidden + (size_t)b * HH);
    const float4* Hbase = (const float4*)(hiddens + (size_t)b * KK * HH)
                        + (size_t)warp * 4 * 256;

    float a0 = 0.f, a1 = 0.f, a2 = 0.f, a3 = 0.f;
    #pragma unroll
    for (int it = 0; it < 8; it++) {
        int idx = it * 32 + lane;                  // coalesced 512B per LDG
        float4 c  = __ldg(&C4[idx]);               // L1-hit after first warp
        float4 x0 = __ldcs(Hbase + idx);
        float4 x1 = __ldcs(Hbase + 256 + idx);
        float4 x2 = __ldcs(Hbase + 512 + idx);
        float4 x3 = __ldcs(Hbase + 768 + idx);
        float d;
        d = c.x - x0.x; a0 += d * d;  d = c.y - x0.y; a0 += d * d;
        d = c.z - x0.z; a0 += d * d;  d = c.w - x0.w; a0 += d * d;
        d = c.x - x1.x; a1 += d * d;  d = c.y - x1.y; a1 += d * d;
        d = c.z - x1.z; a1 += d * d;  d = c.w - x1.w; a1 += d * d;
        d = c.x - x2.x; a2 += d * d;  d = c.y - x2.y; a2 += d * d;
        d = c.z - x2.z; a2 += d * d;  d = c.w - x2.w; a2 += d * d;
        d = c.x - x3.x; a3 += d * d;  d = c.y - x3.y; a3 += d * d;
        d = c.z - x3.z; a3 += d * d;  d = c.w - x3.w; a3 += d * d;
    }
    #pragma unroll
    for (int o = 16; o; o >>= 1) {
        a0 += __shfl_xor_sync(0xffffffffu, a0, o);
        a1 += __shfl_xor_sync(0xffffffffu, a1, o);
        a2 += __shfl_xor_sync(0xffffffffu, a2, o);
        a3 += __shfl_xor_sync(0xffffffffu, a3, o);
    }
    if (lane < 4) {
        float a = (lane == 0) ? a0 : (lane == 1) ? a1 : (lane == 2) ? a2 : a3;
        g_cd[b * KK + warp * 4 + lane] = sqrtf(a);
    }
}

// ---------------- Kernel 2: MLP tail, 16 batches per CTA ----------------
#define W1S 100   // padded row stride (floats); conflict-free LDS.128 per warp
#define JB  16    // batches per CTA

__global__ __launch_bounds__(256, 3) void mlp_kernel(
    const int*   __restrict__ vals,
    const float* __restrict__ distances,
    const float* __restrict__ W1,
    const float* __restrict__ b1,
    const float* __restrict__ W2,
    const float* __restrict__ b2,
    float* __restrict__ out, int N)
{
    __shared__ __align__(16) float sW1[64 * W1S];   // 25.6 KB
    __shared__ __align__(16) float sx[JB][96];      // 6 KB
    __shared__ float shid[JB][64];                  // 4 KB

    const int b0   = blockIdx.x * JB;
    const int tid  = threadIdx.x;
    const int warp = tid >> 5;
    const int lane = tid & 31;

    // stage W1: 1536 float4, coalesced, rows repadded to stride 100
    {
        const float4* g = (const float4*)W1;
        #pragma unroll
        for (int i = 0; i < 6; i++) {
            int m4 = tid + i * 256;
            float4 v = g[m4];
            int m = m4 * 4;
            int r = m / 96, c = m - r * 96;          // float4 never crosses a row
            *(float4*)&sW1[r * W1S + c] = v;
        }
    }

    // warps 0-7: assemble inputs for batches 2*warp, 2*warp+1
    #pragma unroll
    for (int q = 0; q < 2; q++) {
        const int j  = warp * 2 + q;
        const int bb = b0 + j;
        sx[j][lane]      = g_cd[bb * KK + lane];
        sx[j][32 + lane] = distances[bb * KK + lane];
        int v = vals[bb * KK + lane];
        unsigned m = __match_any_sync(0xffffffffu, v);
        int isnew = (v != 0) && ((m & ((1u << lane) - 1u)) == 0);
        int cnt = isnew;
        #pragma unroll
        for (int o = 1; o < 32; o <<= 1) {
            int t = __shfl_up_sync(0xffffffffu, cnt, o);
            if (lane >= o) cnt += t;
        }
        sx[j][64 + lane] = (float)cnt;
    }
    __syncthreads();

    // layer 1: thread = (neuron n, group g); group g computes batches 4g..4g+3.
    // One w read per i feeds 4 batches; x reads are warp broadcasts.
    {
        const int n = tid & 63;
        const int g = tid >> 6;                      // 0..3
        const float4* w4 = (const float4*)&sW1[n * W1S];
        const float4* xa = (const float4*)sx[g * 4 + 0];
        const float4* xb = (const float4*)sx[g * 4 + 1];
        const float4* xc = (const float4*)sx[g * 4 + 2];
        const float4* xd = (const float4*)sx[g * 4 + 3];
        const float bias = __ldg(&b1[n]);
        float acc0 = bias, acc1 = bias, acc2 = bias, acc3 = bias;
        #pragma unroll
        for (int i = 0; i < 24; i++) {
            float4 w = w4[i];
            float4 x;
            x = xa[i]; acc0 += w.x * x.x + w.y * x.y + w.z * x.z + w.w * x.w;
            x = xb[i]; acc1 += w.x * x.x + w.y * x.y + w.z * x.z + w.w * x.w;
            x = xc[i]; acc2 += w.x * x.x + w.y * x.y + w.z * x.z + w.w * x.w;
            x = xd[i]; acc3 += w.x * x.x + w.y * x.y + w.z * x.z + w.w * x.w;
        }
        shid[g * 4 + 0][n] = tanhf(acc0);
        shid[g * 4 + 1][n] = tanhf(acc1);
        shid[g * 4 + 2][n] = tanhf(acc2);
        shid[g * 4 + 3][n] = tanhf(acc3);
    }
    __syncthreads();

    // layer 2 + sigmoid + scale + write: warp w handles batches 2w, 2w+1
    {
        const float w2a = __ldg(&W2[lane]);
        const float w2b = __ldg(&W2[lane + 32]);
        const float bb2 = __ldg(&b2[0]);
        #pragma unroll
        for (int q = 0; q < 2; q++) {
            const int j = warp * 2 + q;
            float s = shid[j][lane] * w2a + shid[j][lane + 32] * w2b;
            #pragma unroll
            for (int o = 16; o; o >>= 1) s += __shfl_xor_sync(0xffffffffu, s, o);
            s += bb2;
            float mu = 1.f / (1.f + expf(-s));
            float scale = __shfl_sync(0xffffffffu, 5.f * mu, 0);
            float cd = sx[j][lane] * scale;
            int o0 = (b0 + j) * KK + lane;
            out[o0]     = cd;
            out[N + o0] = sx[j][32 + lane] + cd;
        }
    }
}

extern "C" void kernel_launch(void* const* d_in, const int* in_sizes, int n_in,
                              void* d_out, int out_size)
{
    const int*   vals         = (const int*)  d_in[0];
    const float* distances    = (const float*)d_in[1];
    const float* cache_hidden = (const float*)d_in[2];
    const float* hiddens      = (const float*)d_in[3];
    const float* W1           = (const float*)d_in[4];
    const float* b1           = (const float*)d_in[5];
    const float* W2           = (const float*)d_in[6];
    const float* b2           = (const float*)d_in[7];
    float* out = (float*)d_out;

    int N = in_sizes[1];              // B*L*K = 262144
    int B = N / KK;                   // 8192

    cdist_kernel<<<B, 256>>>(cache_hidden, hiddens);
    mlp_kernel<<<B / JB, 256>>>(vals, distances, W1, b1, W2, b2, out, N);
}